// round 6
// baseline (speedup 1.0000x reference)
#include <cuda_runtime.h>
#include <math.h>

// Problem constants
#define MDIM 4096
#define NDIM 8192
#define DDIM 64
#define BM   128           // rows per block; grid = 32 blocks of 128 threads

#define EPSV    1e-8f
#define LOGEPS  (-18.420680743952367f)   // log(1e-8), constant

// Global-skip bound: t2 = -0.5*sq/sigma^2 <= 0 always (sq is a squared
// distance), so val = (1/n) * sum exp(t1 + t2) <= exp(t1).
// If t1 <= T1_SKIP (= -46): val <= 1e-20 and
//   |log(EPS + val) - log(EPS)| <= val/EPS <= 1e-12   (below fp32 ulp),
// for ARBITRARY x_eval / x_base — the bound depends only on log_sigma.
#define T1_SKIP (-46.0f)

__device__ __forceinline__ float t1_of(float ls) {
    // t1 = -0.5 * D * log(2*pi) - log_sigma
    return -0.5f * (float)DDIM * 1.8378770664093453f - ls;
}

// ---------------------------------------------------------------------------
// Single kernel, zero dynamic smem.
// Fast path: unconditionally store log(EPS) to our 128 rows (STG.128, no
// dependency on any load), then read log_sigma; if the provable-underflow
// bound holds, exit — the stored constants ARE the exact fp32 answer.
// Fallback (only if t1 > -46; never for this problem's inputs): naive exact
// per-row KDE, overwriting the preliminary stores after a CTA-scope barrier.
// ---------------------------------------------------------------------------
__global__ __launch_bounds__(BM)
void kde_fused(const float* __restrict__ xe,
               const float* __restrict__ xb,
               const float* __restrict__ logsig,
               float* __restrict__ out) {
    const int tid = threadIdx.x;
    const int m0 = blockIdx.x * BM;

    // Preliminary constant stores: 32 x STG.128 covers rows [m0, m0+128).
    if (tid < BM / 4) {
        float4 v = make_float4(LOGEPS, LOGEPS, LOGEPS, LOGEPS);
        ((float4*)(out + m0))[tid] = v;
    }

    const float ls = logsig[0];
    const float t1 = t1_of(ls);
    if (t1 <= T1_SKIP) return;          // provably val <= 1e-20: done.

    // ------------- fallback: exact, simple, never performance-critical ------
    __syncthreads();   // order preliminary stores before our overwrites

    const float inv_s2 = __expf(-2.0f * ls);
    const int row = m0 + tid;           // one row per thread (BM == blockDim)

    // Load this row of x_eval into registers.
    float xr[DDIM];
    const float4* xe4 = (const float4*)(xe + (size_t)row * DDIM);
#pragma unroll
    for (int k = 0; k < DDIM / 4; k++) {
        float4 v = xe4[k];
        xr[4 * k + 0] = v.x;
        xr[4 * k + 1] = v.y;
        xr[4 * k + 2] = v.z;
        xr[4 * k + 3] = v.w;
    }

    float acc = 0.0f;
    for (int j = 0; j < NDIM; j++) {
        const float4* xb4 = (const float4*)(xb + (size_t)j * DDIM);
        float sq = 0.0f;
#pragma unroll
        for (int k = 0; k < DDIM / 4; k++) {
            float4 v = xb4[k];
            float d0 = xr[4 * k + 0] - v.x;
            float d1 = xr[4 * k + 1] - v.y;
            float d2 = xr[4 * k + 2] - v.z;
            float d3 = xr[4 * k + 3] - v.w;
            sq = fmaf(d0, d0, sq);
            sq = fmaf(d1, d1, sq);
            sq = fmaf(d2, d2, sq);
            sq = fmaf(d3, d3, sq);
        }
        acc += expf(t1 - 0.5f * sq * inv_s2);
    }
    out[row] = logf(EPSV + acc * (1.0f / (float)NDIM));
}

// ---------------------------------------------------------------------------
extern "C" void kernel_launch(void* const* d_in, const int* in_sizes, int n_in,
                              void* d_out, int out_size) {
    const float* xe = (const float*)d_in[0];   // x_eval [4096,64]
    const float* xb = (const float*)d_in[1];   // x_base [8192,64]
    const float* ls = (const float*)d_in[2];   // log_sigma [1]
    float* out = (float*)d_out;                // [4096]

    kde_fused<<<MDIM / BM, BM>>>(xe, xb, ls, out);
}